// round 2
// baseline (speedup 1.0000x reference)
#include <cuda_runtime.h>
#include <cuda_bf16.h>
#include <cstdint>

// ---------------------------------------------------------------------------
// QLoRABigNet: 6 blocks x (3 QLoRA linears + relus) + residual + LN
// C=1024, G=128, R=32, N=8192 rows, 18 layers.
// Round 1: fp32 SIMT implementation.
//   - dequant all weights once per launch into g_W (fp32)
//   - per layer: lora u = x@A^T (split-K, two-stage deterministic),
//     main SGEMM y = x@W^T + b + u@B^T (+res)(+relu) fused epilogue
//   - layernorm per row
// ---------------------------------------------------------------------------

#define NROWS 8192
#define CDIM  1024
#define NLAYER 18
#define RDIM  32

// scratch (device globals: allocation-free rule)
__device__ float g_W[(size_t)NLAYER * CDIM * CDIM];   // 75.5 MB dequantized weights
__device__ float g_h[(size_t)NROWS * CDIM];           // residual stream
__device__ float g_t1[(size_t)NROWS * CDIM];
__device__ float g_t2[(size_t)NROWS * CDIM];
__device__ float g_upart[(size_t)8 * NROWS * RDIM];   // split-K partials for lora u
__device__ float g_u[(size_t)NROWS * RDIM];           // u = x @ A^T

// ---------------------------------------------------------------------------
// Dequant: W[l][o][i] = (q - 8) * scales[l][o][i/128], vectorized by 4.
// ---------------------------------------------------------------------------
__global__ void dequant_k(const int* __restrict__ qw,
                          const float* __restrict__ scales,
                          float* __restrict__ Wout, int total4)
{
    int idx = blockIdx.x * blockDim.x + threadIdx.x;
    if (idx >= total4) return;
    int4 q = ((const int4*)qw)[idx];
    size_t base = (size_t)idx * 4;
    int i = (int)(base & 1023);          // position within C_in
    size_t ro = base >> 10;              // l*1024 + o
    float s = scales[ro * 8 + (i >> 7)]; // 4 consecutive i never cross a group
    float4 w;
    w.x = (float)(q.x - 8) * s;
    w.y = (float)(q.y - 8) * s;
    w.z = (float)(q.z - 8) * s;
    w.w = (float)(q.w - 8) * s;
    ((float4*)Wout)[idx] = w;
}

// ---------------------------------------------------------------------------
// LoRA stage 1: partial u over a K-split of 128.
// grid (64 row-tiles, 8 k-splits), 256 threads.
// ---------------------------------------------------------------------------
__global__ void lora_u_partial(const float* __restrict__ X,
                               const float* __restrict__ A,   // [32][1024]
                               float* __restrict__ Up)        // [8][NROWS][32]
{
    __shared__ float sA[32 * 33];
    __shared__ float sX[128 * 33];
    int tid = threadIdx.x;
    int m0 = blockIdx.x * 128;
    int k0 = blockIdx.y * 128;
    int r  = tid & 31;
    int ng = tid >> 5;              // 0..7 -> rows ng*16 .. +15
    float acc[16];
    #pragma unroll
    for (int j = 0; j < 16; j++) acc[j] = 0.f;

    for (int kc = 0; kc < 4; ++kc) {
        int kb = k0 + kc * 32;
        #pragma unroll
        for (int s = 0; s < 4; s++) {
            int f = tid + s * 256;           // 0..1023
            int rr = f >> 5, kk = f & 31;
            sA[rr * 33 + kk] = A[rr * 1024 + kb + kk];
        }
        #pragma unroll
        for (int s = 0; s < 16; s++) {
            int f = tid + s * 256;
            int rr = f >> 5, kk = f & 31;
            sX[rr * 33 + kk] = X[(size_t)(m0 + rr) * CDIM + kb + kk];
        }
        __syncthreads();
        #pragma unroll
        for (int k = 0; k < 32; k++) {
            float a = sA[r * 33 + k];
            #pragma unroll
            for (int j = 0; j < 16; j++)
                acc[j] += sX[(ng * 16 + j) * 33 + k] * a;
        }
        __syncthreads();
    }
    #pragma unroll
    for (int j = 0; j < 16; j++)
        Up[((size_t)blockIdx.y * NROWS + m0 + ng * 16 + j) * RDIM + r] = acc[j];
}

// LoRA stage 2: deterministic fixed-order reduction of the 8 partials.
__global__ void lora_u_reduce(const float* __restrict__ Up, float* __restrict__ U)
{
    int idx = blockIdx.x * blockDim.x + threadIdx.x;   // 0 .. 262143
    float s = 0.f;
    #pragma unroll
    for (int p = 0; p < 8; p++)
        s += Up[(size_t)p * (NROWS * RDIM) + idx];
    U[idx] = s;
}

// ---------------------------------------------------------------------------
// Main fused SGEMM: Out = [relu]( X @ W^T + bias + U @ B^T [+ Res] )
// BM=BN=128, BK=16, TM=TN=8, 256 threads, double-buffered smem.
// grid: (CDIM/128=8, NROWS/128=64)
// ---------------------------------------------------------------------------
__global__ __launch_bounds__(256, 2)
void gemm_fused(const float* __restrict__ X,
                const float* __restrict__ W,     // [1024][1024], o-major, i contiguous
                const float* __restrict__ bias,  // [1024]
                const float* __restrict__ U,     // [NROWS][32]
                const float* __restrict__ Bl,    // [1024][32]
                const float* __restrict__ Res,   // [NROWS][1024] or null
                float* __restrict__ Out,
                int do_relu)
{
    __shared__ __align__(16) float smem[8448];
    float* As = smem;          // 2 x [16][128]
    float* Bs = smem + 4096;   // 2 x [16][128]

    const int tid = threadIdx.x;
    const int tx = tid & 15;
    const int ty = tid >> 4;
    const int m0 = blockIdx.y * 128;
    const int o0 = blockIdx.x * 128;

    float acc[8][8];
    #pragma unroll
    for (int i = 0; i < 8; i++)
        #pragma unroll
        for (int j = 0; j < 8; j++) acc[i][j] = 0.f;

    const int lrow = tid >> 2;   // 0..63
    const int lc4  = tid & 3;    // 0..3
    const float* Xg  = X + (size_t)(m0 + lrow) * CDIM + lc4 * 4;
    const float* Xg2 = Xg + (size_t)64 * CDIM;
    const float* Wg  = W + (size_t)(o0 + lrow) * CDIM + lc4 * 4;
    const float* Wg2 = Wg + (size_t)64 * CDIM;

    // prologue: tile 0 -> buffer 0
    {
        float4 a0 = *(const float4*)Xg;
        float4 a1 = *(const float4*)Xg2;
        float4 b0 = *(const float4*)Wg;
        float4 b1 = *(const float4*)Wg2;
        #pragma unroll
        for (int j = 0; j < 4; j++) {
            As[(lc4 * 4 + j) * 128 + lrow]      = ((float*)&a0)[j];
            As[(lc4 * 4 + j) * 128 + lrow + 64] = ((float*)&a1)[j];
            Bs[(lc4 * 4 + j) * 128 + lrow]      = ((float*)&b0)[j];
            Bs[(lc4 * 4 + j) * 128 + lrow + 64] = ((float*)&b1)[j];
        }
    }
    __syncthreads();

    const int nTiles = CDIM / 16;   // 64
    for (int t = 0; t < nTiles; ++t) {
        int cur = t & 1;
        float4 a0, a1, b0, b1;
        if (t < nTiles - 1) {
            int ko = (t + 1) * 16;
            a0 = *(const float4*)(Xg  + ko);
            a1 = *(const float4*)(Xg2 + ko);
            b0 = *(const float4*)(Wg  + ko);
            b1 = *(const float4*)(Wg2 + ko);
        }
        const float* Ac = As + cur * 2048;
        const float* Bc = Bs + cur * 2048;
        #pragma unroll
        for (int k = 0; k < 16; k++) {
            float a[8], b[8];
            *(float4*)&a[0] = *(const float4*)&Ac[k * 128 + ty * 8];
            *(float4*)&a[4] = *(const float4*)&Ac[k * 128 + ty * 8 + 4];
            *(float4*)&b[0] = *(const float4*)&Bc[k * 128 + tx * 8];
            *(float4*)&b[4] = *(const float4*)&Bc[k * 128 + tx * 8 + 4];
            #pragma unroll
            for (int i = 0; i < 8; i++)
                #pragma unroll
                for (int j = 0; j < 8; j++)
                    acc[i][j] += a[i] * b[j];
        }
        if (t < nTiles - 1) {
            int nb = cur ^ 1;
            float* An = As + nb * 2048;
            float* Bn = Bs + nb * 2048;
            #pragma unroll
            for (int j = 0; j < 4; j++) {
                An[(lc4 * 4 + j) * 128 + lrow]      = ((float*)&a0)[j];
                An[(lc4 * 4 + j) * 128 + lrow + 64] = ((float*)&a1)[j];
                Bn[(lc4 * 4 + j) * 128 + lrow]      = ((float*)&b0)[j];
                Bn[(lc4 * 4 + j) * 128 + lrow + 64] = ((float*)&b1)[j];
            }
        }
        __syncthreads();
    }

    // ---- epilogue: LoRA rank-32 contribution (reuse smem) ----
    // Su: [128][32] at smem[0], Sb: [128] rows, stride 33, at smem+4096
    {
        const float4* Ug = (const float4*)(U + (size_t)m0 * RDIM);
        float4* Su4 = (float4*)smem;
        #pragma unroll
        for (int s = 0; s < 4; s++)
            Su4[tid + s * 256] = Ug[tid + s * 256];
        #pragma unroll
        for (int s = 0; s < 4; s++) {
            int f = tid + s * 256;       // float4 index, row = f/8
            int row = f >> 3, c4 = f & 7;
            float4 v = *(const float4*)(Bl + (size_t)(o0 + row) * RDIM + c4 * 4);
            float* dst = smem + 4096 + row * 33 + c4 * 4;
            dst[0] = v.x; dst[1] = v.y; dst[2] = v.z; dst[3] = v.w;
        }
    }
    __syncthreads();

    #pragma unroll
    for (int r = 0; r < RDIM; r++) {
        float uu[8], bb[8];
        #pragma unroll
        for (int i = 0; i < 8; i++) uu[i] = smem[(ty * 8 + i) * 32 + r];
        #pragma unroll
        for (int j = 0; j < 8; j++) bb[j] = smem[4096 + (tx * 8 + j) * 33 + r];
        #pragma unroll
        for (int i = 0; i < 8; i++)
            #pragma unroll
            for (int j = 0; j < 8; j++)
                acc[i][j] += uu[i] * bb[j];
    }

    // bias + residual + relu + store
    float bs[8];
    #pragma unroll
    for (int j = 0; j < 8; j++) bs[j] = bias[o0 + tx * 8 + j];

    #pragma unroll
    for (int i = 0; i < 8; i++) {
        int row = m0 + ty * 8 + i;
        float* op = Out + (size_t)row * CDIM + o0 + tx * 8;
        float rv[8];
        if (Res) {
            const float* rp = Res + (size_t)row * CDIM + o0 + tx * 8;
            *(float4*)&rv[0] = *(const float4*)&rp[0];
            *(float4*)&rv[4] = *(const float4*)&rp[4];
        }
        float o[8];
        #pragma unroll
        for (int j = 0; j < 8; j++) {
            float v = acc[i][j] + bs[j];
            if (Res) v += rv[j];
            if (do_relu) v = fmaxf(v, 0.f);
            o[j] = v;
        }
        *(float4*)&op[0] = *(const float4*)&o[0];
        *(float4*)&op[4] = *(const float4*)&o[4];
    }
}

// ---------------------------------------------------------------------------
// LayerNorm, one CTA (256 threads) per row, in-place.
// ---------------------------------------------------------------------------
__global__ void layernorm_k(float* __restrict__ H,
                            const float* __restrict__ g,
                            const float* __restrict__ b)
{
    __shared__ float red[16];
    int row = blockIdx.x;
    float4* hp = (float4*)(H + (size_t)row * CDIM);
    int tid = threadIdx.x;      // 256, each handles 4 floats
    float4 x = hp[tid];

    float s = x.x + x.y + x.z + x.w;
    #pragma unroll
    for (int o = 16; o > 0; o >>= 1) s += __shfl_xor_sync(0xffffffffu, s, o);
    if ((tid & 31) == 0) red[tid >> 5] = s;
    __syncthreads();
    float tot = 0.f;
    #pragma unroll
    for (int w = 0; w < 8; w++) tot += red[w];
    float mean = tot * (1.f / 1024.f);

    float d0 = x.x - mean, d1 = x.y - mean, d2 = x.z - mean, d3 = x.w - mean;
    float sq = d0 * d0 + d1 * d1 + d2 * d2 + d3 * d3;
    #pragma unroll
    for (int o = 16; o > 0; o >>= 1) sq += __shfl_xor_sync(0xffffffffu, sq, o);
    if ((tid & 31) == 0) red[8 + (tid >> 5)] = sq;
    __syncthreads();
    float tot2 = 0.f;
    #pragma unroll
    for (int w = 0; w < 8; w++) tot2 += red[8 + w];
    float inv = rsqrtf(tot2 * (1.f / 1024.f) + 1e-5f);

    float4 gg = ((const float4*)g)[tid];
    float4 bb = ((const float4*)b)[tid];
    float4 y;
    y.x = d0 * inv * gg.x + bb.x;
    y.y = d1 * inv * gg.y + bb.y;
    y.z = d2 * inv * gg.z + bb.z;
    y.w = d3 * inv * gg.w + bb.w;
    hp[tid] = y;
}

// ---------------------------------------------------------------------------
extern "C" void kernel_launch(void* const* d_in, const int* in_sizes, int n_in,
                              void* d_out, int out_size)
{
    const float* x      = (const float*)d_in[0];
    const int*   qw     = (const int*)  d_in[1];
    const float* scales = (const float*)d_in[2];
    const float* bias   = (const float*)d_in[3];
    const float* la     = (const float*)d_in[4];   // [18][32][1024]
    const float* lb     = (const float*)d_in[5];   // [18][1024][32]
    const float* ln_g   = (const float*)d_in[6];   // [5][1024]
    const float* ln_b   = (const float*)d_in[7];
    float* out = (float*)d_out;

    float *W, *h, *t1, *t2, *up, *u;
    cudaGetSymbolAddress((void**)&W,  g_W);
    cudaGetSymbolAddress((void**)&h,  g_h);
    cudaGetSymbolAddress((void**)&t1, g_t1);
    cudaGetSymbolAddress((void**)&t2, g_t2);
    cudaGetSymbolAddress((void**)&up, g_upart);
    cudaGetSymbolAddress((void**)&u,  g_u);

    // dequant all 18 weight matrices (18*1024*1024/4 float4s)
    dequant_k<<<18432, 256>>>(qw, scales, W, 4718592);

    auto run_layer = [&](const float* in, int l, float* outp, bool relu,
                         const float* res) {
        lora_u_partial<<<dim3(64, 8), 256>>>(in, la + (size_t)l * RDIM * CDIM, up);
        lora_u_reduce<<<1024, 256>>>(up, u);
        gemm_fused<<<dim3(8, 64), 256>>>(in,
                                         W + (size_t)l * CDIM * CDIM,
                                         bias + (size_t)l * CDIM,
                                         u,
                                         lb + (size_t)l * CDIM * RDIM,
                                         res, outp, relu ? 1 : 0);
    };

    for (int blk = 0; blk < 6; ++blk) {
        const float* h_in = (blk == 0) ? x : h;
        int l = blk * 3;
        run_layer(h_in, l,     t1, true,  nullptr);
        run_layer(t1,   l + 1, t2, true,  nullptr);
        float* outp = (blk == 5) ? out : h;
        run_layer(t2,   l + 2, outp, false, h_in);   // + block residual
        if (blk < 5)
            layernorm_k<<<NROWS, 256>>>(h, ln_g + (size_t)blk * CDIM,
                                           ln_b + (size_t)blk * CDIM);
    }
}

// round 3
// speedup vs baseline: 1.0021x; 1.0021x over previous
#include <cuda_runtime.h>
#include <cuda_bf16.h>
#include <cstdint>

// ---------------------------------------------------------------------------
// QLoRABigNet: 6 blocks x (3 QLoRA linears + relus) + residual + LN
// C=1024, G=128, R=32, N=8192 rows, 18 layers.
// Round 1: fp32 SIMT implementation.
//   - dequant all weights once per launch into g_W (fp32)
//   - per layer: lora u = x@A^T (split-K, two-stage deterministic),
//     main SGEMM y = x@W^T + b + u@B^T (+res)(+relu) fused epilogue
//   - layernorm per row
// ---------------------------------------------------------------------------

#define NROWS 8192
#define CDIM  1024
#define NLAYER 18
#define RDIM  32

// scratch (device globals: allocation-free rule)
__device__ float g_W[(size_t)NLAYER * CDIM * CDIM];   // 75.5 MB dequantized weights
__device__ float g_h[(size_t)NROWS * CDIM];           // residual stream
__device__ float g_t1[(size_t)NROWS * CDIM];
__device__ float g_t2[(size_t)NROWS * CDIM];
__device__ float g_upart[(size_t)8 * NROWS * RDIM];   // split-K partials for lora u
__device__ float g_u[(size_t)NROWS * RDIM];           // u = x @ A^T

// ---------------------------------------------------------------------------
// Dequant: W[l][o][i] = (q - 8) * scales[l][o][i/128], vectorized by 4.
// ---------------------------------------------------------------------------
__global__ void dequant_k(const int* __restrict__ qw,
                          const float* __restrict__ scales,
                          float* __restrict__ Wout, int total4)
{
    int idx = blockIdx.x * blockDim.x + threadIdx.x;
    if (idx >= total4) return;
    int4 q = ((const int4*)qw)[idx];
    size_t base = (size_t)idx * 4;
    int i = (int)(base & 1023);          // position within C_in
    size_t ro = base >> 10;              // l*1024 + o
    float s = scales[ro * 8 + (i >> 7)]; // 4 consecutive i never cross a group
    float4 w;
    w.x = (float)(q.x - 8) * s;
    w.y = (float)(q.y - 8) * s;
    w.z = (float)(q.z - 8) * s;
    w.w = (float)(q.w - 8) * s;
    ((float4*)Wout)[idx] = w;
}

// ---------------------------------------------------------------------------
// LoRA stage 1: partial u over a K-split of 128.
// grid (64 row-tiles, 8 k-splits), 256 threads.
// ---------------------------------------------------------------------------
__global__ void lora_u_partial(const float* __restrict__ X,
                               const float* __restrict__ A,   // [32][1024]
                               float* __restrict__ Up)        // [8][NROWS][32]
{
    __shared__ float sA[32 * 33];
    __shared__ float sX[128 * 33];
    int tid = threadIdx.x;
    int m0 = blockIdx.x * 128;
    int k0 = blockIdx.y * 128;
    int r  = tid & 31;
    int ng = tid >> 5;              // 0..7 -> rows ng*16 .. +15
    float acc[16];
    #pragma unroll
    for (int j = 0; j < 16; j++) acc[j] = 0.f;

    for (int kc = 0; kc < 4; ++kc) {
        int kb = k0 + kc * 32;
        #pragma unroll
        for (int s = 0; s < 4; s++) {
            int f = tid + s * 256;           // 0..1023
            int rr = f >> 5, kk = f & 31;
            sA[rr * 33 + kk] = A[rr * 1024 + kb + kk];
        }
        #pragma unroll
        for (int s = 0; s < 16; s++) {
            int f = tid + s * 256;
            int rr = f >> 5, kk = f & 31;
            sX[rr * 33 + kk] = X[(size_t)(m0 + rr) * CDIM + kb + kk];
        }
        __syncthreads();
        #pragma unroll
        for (int k = 0; k < 32; k++) {
            float a = sA[r * 33 + k];
            #pragma unroll
            for (int j = 0; j < 16; j++)
                acc[j] += sX[(ng * 16 + j) * 33 + k] * a;
        }
        __syncthreads();
    }
    #pragma unroll
    for (int j = 0; j < 16; j++)
        Up[((size_t)blockIdx.y * NROWS + m0 + ng * 16 + j) * RDIM + r] = acc[j];
}

// LoRA stage 2: deterministic fixed-order reduction of the 8 partials.
__global__ void lora_u_reduce(const float* __restrict__ Up, float* __restrict__ U)
{
    int idx = blockIdx.x * blockDim.x + threadIdx.x;   // 0 .. 262143
    float s = 0.f;
    #pragma unroll
    for (int p = 0; p < 8; p++)
        s += Up[(size_t)p * (NROWS * RDIM) + idx];
    U[idx] = s;
}

// ---------------------------------------------------------------------------
// Main fused SGEMM: Out = [relu]( X @ W^T + bias + U @ B^T [+ Res] )
// BM=BN=128, BK=16, TM=TN=8, 256 threads, double-buffered smem.
// grid: (CDIM/128=8, NROWS/128=64)
// ---------------------------------------------------------------------------
__global__ __launch_bounds__(256, 2)
void gemm_fused(const float* __restrict__ X,
                const float* __restrict__ W,     // [1024][1024], o-major, i contiguous
                const float* __restrict__ bias,  // [1024]
                const float* __restrict__ U,     // [NROWS][32]
                const float* __restrict__ Bl,    // [1024][32]
                const float* __restrict__ Res,   // [NROWS][1024] or null
                float* __restrict__ Out,
                int do_relu)
{
    __shared__ __align__(16) float smem[8448];
    float* As = smem;          // 2 x [16][128]
    float* Bs = smem + 4096;   // 2 x [16][128]

    const int tid = threadIdx.x;
    const int tx = tid & 15;
    const int ty = tid >> 4;
    const int m0 = blockIdx.y * 128;
    const int o0 = blockIdx.x * 128;

    float acc[8][8];
    #pragma unroll
    for (int i = 0; i < 8; i++)
        #pragma unroll
        for (int j = 0; j < 8; j++) acc[i][j] = 0.f;

    const int lrow = tid >> 2;   // 0..63
    const int lc4  = tid & 3;    // 0..3
    const float* Xg  = X + (size_t)(m0 + lrow) * CDIM + lc4 * 4;
    const float* Xg2 = Xg + (size_t)64 * CDIM;
    const float* Wg  = W + (size_t)(o0 + lrow) * CDIM + lc4 * 4;
    const float* Wg2 = Wg + (size_t)64 * CDIM;

    // prologue: tile 0 -> buffer 0
    {
        float4 a0 = *(const float4*)Xg;
        float4 a1 = *(const float4*)Xg2;
        float4 b0 = *(const float4*)Wg;
        float4 b1 = *(const float4*)Wg2;
        #pragma unroll
        for (int j = 0; j < 4; j++) {
            As[(lc4 * 4 + j) * 128 + lrow]      = ((float*)&a0)[j];
            As[(lc4 * 4 + j) * 128 + lrow + 64] = ((float*)&a1)[j];
            Bs[(lc4 * 4 + j) * 128 + lrow]      = ((float*)&b0)[j];
            Bs[(lc4 * 4 + j) * 128 + lrow + 64] = ((float*)&b1)[j];
        }
    }
    __syncthreads();

    const int nTiles = CDIM / 16;   // 64
    for (int t = 0; t < nTiles; ++t) {
        int cur = t & 1;
        float4 a0, a1, b0, b1;
        if (t < nTiles - 1) {
            int ko = (t + 1) * 16;
            a0 = *(const float4*)(Xg  + ko);
            a1 = *(const float4*)(Xg2 + ko);
            b0 = *(const float4*)(Wg  + ko);
            b1 = *(const float4*)(Wg2 + ko);
        }
        const float* Ac = As + cur * 2048;
        const float* Bc = Bs + cur * 2048;
        #pragma unroll
        for (int k = 0; k < 16; k++) {
            float a[8], b[8];
            *(float4*)&a[0] = *(const float4*)&Ac[k * 128 + ty * 8];
            *(float4*)&a[4] = *(const float4*)&Ac[k * 128 + ty * 8 + 4];
            *(float4*)&b[0] = *(const float4*)&Bc[k * 128 + tx * 8];
            *(float4*)&b[4] = *(const float4*)&Bc[k * 128 + tx * 8 + 4];
            #pragma unroll
            for (int i = 0; i < 8; i++)
                #pragma unroll
                for (int j = 0; j < 8; j++)
                    acc[i][j] += a[i] * b[j];
        }
        if (t < nTiles - 1) {
            int nb = cur ^ 1;
            float* An = As + nb * 2048;
            float* Bn = Bs + nb * 2048;
            #pragma unroll
            for (int j = 0; j < 4; j++) {
                An[(lc4 * 4 + j) * 128 + lrow]      = ((float*)&a0)[j];
                An[(lc4 * 4 + j) * 128 + lrow + 64] = ((float*)&a1)[j];
                Bn[(lc4 * 4 + j) * 128 + lrow]      = ((float*)&b0)[j];
                Bn[(lc4 * 4 + j) * 128 + lrow + 64] = ((float*)&b1)[j];
            }
        }
        __syncthreads();
    }

    // ---- epilogue: LoRA rank-32 contribution (reuse smem) ----
    // Su: [128][32] at smem[0], Sb: [128] rows, stride 33, at smem+4096
    {
        const float4* Ug = (const float4*)(U + (size_t)m0 * RDIM);
        float4* Su4 = (float4*)smem;
        #pragma unroll
        for (int s = 0; s < 4; s++)
            Su4[tid + s * 256] = Ug[tid + s * 256];
        #pragma unroll
        for (int s = 0; s < 4; s++) {
            int f = tid + s * 256;       // float4 index, row = f/8
            int row = f >> 3, c4 = f & 7;
            float4 v = *(const float4*)(Bl + (size_t)(o0 + row) * RDIM + c4 * 4);
            float* dst = smem + 4096 + row * 33 + c4 * 4;
            dst[0] = v.x; dst[1] = v.y; dst[2] = v.z; dst[3] = v.w;
        }
    }
    __syncthreads();

    #pragma unroll
    for (int r = 0; r < RDIM; r++) {
        float uu[8], bb[8];
        #pragma unroll
        for (int i = 0; i < 8; i++) uu[i] = smem[(ty * 8 + i) * 32 + r];
        #pragma unroll
        for (int j = 0; j < 8; j++) bb[j] = smem[4096 + (tx * 8 + j) * 33 + r];
        #pragma unroll
        for (int i = 0; i < 8; i++)
            #pragma unroll
            for (int j = 0; j < 8; j++)
                acc[i][j] += uu[i] * bb[j];
    }

    // bias + residual + relu + store
    float bs[8];
    #pragma unroll
    for (int j = 0; j < 8; j++) bs[j] = bias[o0 + tx * 8 + j];

    #pragma unroll
    for (int i = 0; i < 8; i++) {
        int row = m0 + ty * 8 + i;
        float* op = Out + (size_t)row * CDIM + o0 + tx * 8;
        float rv[8];
        if (Res) {
            const float* rp = Res + (size_t)row * CDIM + o0 + tx * 8;
            *(float4*)&rv[0] = *(const float4*)&rp[0];
            *(float4*)&rv[4] = *(const float4*)&rp[4];
        }
        float o[8];
        #pragma unroll
        for (int j = 0; j < 8; j++) {
            float v = acc[i][j] + bs[j];
            if (Res) v += rv[j];
            if (do_relu) v = fmaxf(v, 0.f);
            o[j] = v;
        }
        *(float4*)&op[0] = *(const float4*)&o[0];
        *(float4*)&op[4] = *(const float4*)&o[4];
    }
}

// ---------------------------------------------------------------------------
// LayerNorm, one CTA (256 threads) per row, in-place.
// ---------------------------------------------------------------------------
__global__ void layernorm_k(float* __restrict__ H,
                            const float* __restrict__ g,
                            const float* __restrict__ b)
{
    __shared__ float red[16];
    int row = blockIdx.x;
    float4* hp = (float4*)(H + (size_t)row * CDIM);
    int tid = threadIdx.x;      // 256, each handles 4 floats
    float4 x = hp[tid];

    float s = x.x + x.y + x.z + x.w;
    #pragma unroll
    for (int o = 16; o > 0; o >>= 1) s += __shfl_xor_sync(0xffffffffu, s, o);
    if ((tid & 31) == 0) red[tid >> 5] = s;
    __syncthreads();
    float tot = 0.f;
    #pragma unroll
    for (int w = 0; w < 8; w++) tot += red[w];
    float mean = tot * (1.f / 1024.f);

    float d0 = x.x - mean, d1 = x.y - mean, d2 = x.z - mean, d3 = x.w - mean;
    float sq = d0 * d0 + d1 * d1 + d2 * d2 + d3 * d3;
    #pragma unroll
    for (int o = 16; o > 0; o >>= 1) sq += __shfl_xor_sync(0xffffffffu, sq, o);
    if ((tid & 31) == 0) red[8 + (tid >> 5)] = sq;
    __syncthreads();
    float tot2 = 0.f;
    #pragma unroll
    for (int w = 0; w < 8; w++) tot2 += red[8 + w];
    float inv = rsqrtf(tot2 * (1.f / 1024.f) + 1e-5f);

    float4 gg = ((const float4*)g)[tid];
    float4 bb = ((const float4*)b)[tid];
    float4 y;
    y.x = d0 * inv * gg.x + bb.x;
    y.y = d1 * inv * gg.y + bb.y;
    y.z = d2 * inv * gg.z + bb.z;
    y.w = d3 * inv * gg.w + bb.w;
    hp[tid] = y;
}

// ---------------------------------------------------------------------------
extern "C" void kernel_launch(void* const* d_in, const int* in_sizes, int n_in,
                              void* d_out, int out_size)
{
    const float* x      = (const float*)d_in[0];
    const int*   qw     = (const int*)  d_in[1];
    const float* scales = (const float*)d_in[2];
    const float* bias   = (const float*)d_in[3];
    const float* la     = (const float*)d_in[4];   // [18][32][1024]
    const float* lb     = (const float*)d_in[5];   // [18][1024][32]
    const float* ln_g   = (const float*)d_in[6];   // [5][1024]
    const float* ln_b   = (const float*)d_in[7];
    float* out = (float*)d_out;

    float *W, *h, *t1, *t2, *up, *u;
    cudaGetSymbolAddress((void**)&W,  g_W);
    cudaGetSymbolAddress((void**)&h,  g_h);
    cudaGetSymbolAddress((void**)&t1, g_t1);
    cudaGetSymbolAddress((void**)&t2, g_t2);
    cudaGetSymbolAddress((void**)&up, g_upart);
    cudaGetSymbolAddress((void**)&u,  g_u);

    // dequant all 18 weight matrices (18*1024*1024/4 float4s)
    dequant_k<<<18432, 256>>>(qw, scales, W, 4718592);

    auto run_layer = [&](const float* in, int l, float* outp, bool relu,
                         const float* res) {
        lora_u_partial<<<dim3(64, 8), 256>>>(in, la + (size_t)l * RDIM * CDIM, up);
        lora_u_reduce<<<1024, 256>>>(up, u);
        gemm_fused<<<dim3(8, 64), 256>>>(in,
                                         W + (size_t)l * CDIM * CDIM,
                                         bias + (size_t)l * CDIM,
                                         u,
                                         lb + (size_t)l * CDIM * RDIM,
                                         res, outp, relu ? 1 : 0);
    };

    for (int blk = 0; blk < 6; ++blk) {
        const float* h_in = (blk == 0) ? x : h;
        int l = blk * 3;
        run_layer(h_in, l,     t1, true,  nullptr);
        run_layer(t1,   l + 1, t2, true,  nullptr);
        float* outp = (blk == 5) ? out : h;
        run_layer(t2,   l + 2, outp, false, h_in);   // + block residual
        if (blk < 5)
            layernorm_k<<<NROWS, 256>>>(h, ln_g + (size_t)blk * CDIM,
                                           ln_b + (size_t)blk * CDIM);
    }
}

// round 7
// speedup vs baseline: 1.6102x; 1.6069x over previous
#include <cuda_runtime.h>
#include <cuda_bf16.h>
#include <cstdint>

// ---------------------------------------------------------------------------
// QLoRABigNet via mma.sync bf16 3-term split (Xh*Wh + Xh*Wl + Xl*Wh), fp32 acc.
// (tcgen05 unavailable: harness compiles for plain sm_100.)
// LoRA folded as a 33rd K-chunk. Fused bias/residual/relu epilogue that also
// emits the next layer's bf16 hi/lo activation planes.
// ---------------------------------------------------------------------------

#define NROWS 8192
#define CDIM  1024
#define NLAYER 18
#define RDIM  32

typedef __nv_bfloat16 bf16;

// ---------------- device scratch ----------------
__device__ bf16 g_Whi[(size_t)NLAYER * CDIM * CDIM];
__device__ bf16 g_Wlo[(size_t)NLAYER * CDIM * CDIM];
__device__ bf16 g_Ah0[(size_t)NROWS * CDIM];
__device__ bf16 g_Al0[(size_t)NROWS * CDIM];
__device__ bf16 g_Ah1[(size_t)NROWS * CDIM];
__device__ bf16 g_Al1[(size_t)NROWS * CDIM];
__device__ float g_h [(size_t)NROWS * CDIM];
__device__ float g_t1[(size_t)NROWS * CDIM];
__device__ float g_t2[(size_t)NROWS * CDIM];
__device__ float g_upart[(size_t)8 * NROWS * RDIM];
__device__ bf16 g_Uh[(size_t)NROWS * 64];            // padded to 64 (use k 0..31)
__device__ bf16 g_Ul[(size_t)NROWS * 64];
__device__ bf16 g_BLh[(size_t)NLAYER * CDIM * 64];
__device__ bf16 g_BLl[(size_t)NLAYER * CDIM * 64];

// ---------------- helpers ----------------
__device__ __forceinline__ uint32_t pack_hi2(float a, float b) {
    __nv_bfloat162 t = __floats2bfloat162_rn(a, b);
    return *reinterpret_cast<uint32_t*>(&t);
}
__device__ __forceinline__ uint32_t pack_lo2(float a, float b) {
    float ah = __bfloat162float(__float2bfloat16(a));
    float bh = __bfloat162float(__float2bfloat16(b));
    __nv_bfloat162 t = __floats2bfloat162_rn(a - ah, b - bh);
    return *reinterpret_cast<uint32_t*>(&t);
}
__device__ __forceinline__ uint32_t smem_u32(const void* p) {
    uint32_t a;
    asm("{ .reg .u64 t; cvta.to.shared.u64 t, %1; cvt.u32.u64 %0, t; }"
        : "=r"(a) : "l"(p));
    return a;
}
__device__ __forceinline__ void cp16(uint32_t dst, const void* src) {
    asm volatile("cp.async.cg.shared.global [%0], [%1], 16;"
                 :: "r"(dst), "l"(src) : "memory");
}
__device__ __forceinline__ void cp_commit() {
    asm volatile("cp.async.commit_group;" ::: "memory");
}
template <int N>
__device__ __forceinline__ void cp_wait() {
    asm volatile("cp.async.wait_group %0;" :: "n"(N) : "memory");
}
__device__ __forceinline__ void mma16816(float* d, const uint32_t* a,
                                         const uint32_t* b) {
    asm volatile(
        "mma.sync.aligned.m16n8k16.row.col.f32.bf16.bf16.f32 "
        "{%0,%1,%2,%3}, {%4,%5,%6,%7}, {%8,%9}, {%0,%1,%2,%3};"
        : "+f"(d[0]), "+f"(d[1]), "+f"(d[2]), "+f"(d[3])
        : "r"(a[0]), "r"(a[1]), "r"(a[2]), "r"(a[3]), "r"(b[0]), "r"(b[1]));
}

// ---------------- prep kernels ----------------
__global__ void dequant_whl(const int* __restrict__ qw,
                            const float* __restrict__ scales,
                            bf16* __restrict__ Wh, bf16* __restrict__ Wl,
                            int total4)
{
    int idx = blockIdx.x * blockDim.x + threadIdx.x;
    if (idx >= total4) return;
    int4 q = ((const int4*)qw)[idx];
    size_t base = (size_t)idx * 4;
    int i = (int)(base & 1023);
    size_t ro = base >> 10;
    float s = scales[ro * 8 + (i >> 7)];
    float w0 = (float)(q.x - 8) * s, w1 = (float)(q.y - 8) * s;
    float w2 = (float)(q.z - 8) * s, w3 = (float)(q.w - 8) * s;
    uint2 h; h.x = pack_hi2(w0, w1); h.y = pack_hi2(w2, w3);
    uint2 l; l.x = pack_lo2(w0, w1); l.y = pack_lo2(w2, w3);
    ((uint2*)Wh)[idx] = h;
    ((uint2*)Wl)[idx] = l;
}

__global__ void prep_lb(const float* __restrict__ lb,
                        bf16* __restrict__ BLh, bf16* __restrict__ BLl)
{
    int idx = blockIdx.x * blockDim.x + threadIdx.x;   // 18*1024*64
    int col = idx & 63;
    int ro  = idx >> 6;
    float v = (col < 32) ? lb[(size_t)ro * 32 + col] : 0.f;
    bf16 hi = __float2bfloat16(v);
    BLh[idx] = hi;
    BLl[idx] = __float2bfloat16(v - __bfloat162float(hi));
}

__global__ void prep_x(const float* __restrict__ X,
                       bf16* __restrict__ H, bf16* __restrict__ L)
{
    int idx = blockIdx.x * blockDim.x + threadIdx.x;   // 2M float4s
    float4 v = ((const float4*)X)[idx];
    uint2 h; h.x = pack_hi2(v.x, v.y); h.y = pack_hi2(v.z, v.w);
    uint2 l; l.x = pack_lo2(v.x, v.y); l.y = pack_lo2(v.z, v.w);
    ((uint2*)H)[idx] = h;
    ((uint2*)L)[idx] = l;
}

// ---------------- LoRA u = x @ A^T (split-K, fp32) ----------------
__global__ void lora_u_partial(const float* __restrict__ X,
                               const float* __restrict__ A,
                               float* __restrict__ Up)
{
    __shared__ float sA[32 * 33];
    __shared__ float sX[128 * 33];
    int tid = threadIdx.x;
    int m0 = blockIdx.x * 128;
    int k0 = blockIdx.y * 128;
    int r  = tid & 31;
    int ng = tid >> 5;
    float acc[16];
    #pragma unroll
    for (int j = 0; j < 16; j++) acc[j] = 0.f;

    for (int kc = 0; kc < 4; ++kc) {
        int kb = k0 + kc * 32;
        #pragma unroll
        for (int s = 0; s < 4; s++) {
            int f = tid + s * 256;
            sA[(f >> 5) * 33 + (f & 31)] = A[(f >> 5) * 1024 + kb + (f & 31)];
        }
        #pragma unroll
        for (int s = 0; s < 16; s++) {
            int f = tid + s * 256;
            sX[(f >> 5) * 33 + (f & 31)] =
                X[(size_t)(m0 + (f >> 5)) * CDIM + kb + (f & 31)];
        }
        __syncthreads();
        #pragma unroll
        for (int k = 0; k < 32; k++) {
            float a = sA[r * 33 + k];
            #pragma unroll
            for (int j = 0; j < 16; j++)
                acc[j] += sX[(ng * 16 + j) * 33 + k] * a;
        }
        __syncthreads();
    }
    #pragma unroll
    for (int j = 0; j < 16; j++)
        Up[((size_t)blockIdx.y * NROWS + m0 + ng * 16 + j) * RDIM + r] = acc[j];
}

__global__ void lora_u_reduce(const float* __restrict__ Up,
                              bf16* __restrict__ Uh, bf16* __restrict__ Ul)
{
    int idx = blockIdx.x * blockDim.x + threadIdx.x;   // 0..262143
    float s = 0.f;
    #pragma unroll
    for (int p = 0; p < 8; p++)
        s += Up[(size_t)p * (NROWS * RDIM) + idx];
    int row = idx >> 5, c = idx & 31;
    bf16 hi = __float2bfloat16(s);
    Uh[(size_t)row * 64 + c] = hi;
    Ul[(size_t)row * 64 + c] = __float2bfloat16(s - __bfloat162float(hi));
}

// ---------------- mma.sync GEMM ----------------
// CTA 128x128, 8 warps (2M x 4N), warp tile 64x32, BK=32, 2-stage cp.async.
// smem per stage: 4 planes (Xh,Xl,Wh,Wl) of 128 rows x 40 bf16 (80B) = 40960B.
#define ROWB 80
#define PLANE_BYTES 10240
#define STAGE_BYTES 40960
#define SMEM_TOTAL  81920
#define NCHUNK 33

__device__ __forceinline__ void load_chunk(
    uint32_t sb, int stage, int t, int m0, int o0, int tid,
    const bf16* Xh, const bf16* Xl, const bf16* Wh, const bf16* Wl,
    const bf16* Uh, const bf16* Ul, const bf16* BLh, const bf16* BLl)
{
    uint32_t base = sb + stage * STAGE_BYTES;
    const char *pA, *pB, *pC, *pD;
    size_t strA, strW;
    if (t < 32) {
        size_t off = (size_t)t * 64;                    // k0*2 bytes
        pA = (const char*)Xh + (size_t)m0 * 2048 + off;
        pB = (const char*)Xl + (size_t)m0 * 2048 + off;
        pC = (const char*)Wh + (size_t)o0 * 2048 + off;
        pD = (const char*)Wl + (size_t)o0 * 2048 + off;
        strA = 2048; strW = 2048;
    } else {                                            // lora chunk, k0=0
        pA = (const char*)Uh + (size_t)m0 * 128;
        pB = (const char*)Ul + (size_t)m0 * 128;
        pC = (const char*)BLh + (size_t)o0 * 128;
        pD = (const char*)BLl + (size_t)o0 * 128;
        strA = 128; strW = 128;
    }
    int r = tid & 127;
    int cbase = (tid >> 7) * 2;                          // 0 or 2
    #pragma unroll
    for (int j = 0; j < 2; j++) {
        int c16 = cbase + j;                             // 0..3 (16B chunks)
        uint32_t sw = (uint32_t)(r * ROWB + c16 * 16);
        size_t goA = (size_t)r * strA + c16 * 16;
        size_t goW = (size_t)r * strW + c16 * 16;
        cp16(base + sw,                   pA + goA);
        cp16(base + PLANE_BYTES + sw,     pB + goA);
        cp16(base + 2 * PLANE_BYTES + sw, pC + goW);
        cp16(base + 3 * PLANE_BYTES + sw, pD + goW);
    }
    cp_commit();
}

__global__ __launch_bounds__(256, 2)
void gemm_mma(const bf16* __restrict__ Xh, const bf16* __restrict__ Xl,
              const bf16* __restrict__ Wh, const bf16* __restrict__ Wl,
              const float* __restrict__ bias,
              const bf16* __restrict__ Uh, const bf16* __restrict__ Ul,
              const bf16* __restrict__ BLh, const bf16* __restrict__ BLl,
              const float* __restrict__ Res,
              float* __restrict__ OutF,
              bf16* __restrict__ OutH, bf16* __restrict__ OutL,
              int do_relu)
{
    extern __shared__ char smem[];
    const int tid = threadIdx.x;
    const int wid = tid >> 5;
    const int lane = tid & 31;
    const int g = lane >> 2;          // 0..7
    const int tq = lane & 3;          // 0..3
    const int wm = (wid & 1) * 64;    // warp M offset
    const int wn = (wid >> 1) * 32;   // warp N offset
    const int o0 = blockIdx.x * 128;
    const int m0 = blockIdx.y * 128;
    uint32_t sb = smem_u32(smem);

    float acc[4][4][4];
    #pragma unroll
    for (int a = 0; a < 4; a++)
        #pragma unroll
        for (int b = 0; b < 4; b++)
            #pragma unroll
            for (int c = 0; c < 4; c++) acc[a][b][c] = 0.f;

    load_chunk(sb, 0, 0, m0, o0, tid, Xh, Xl, Wh, Wl, Uh, Ul, BLh, BLl);
    load_chunk(sb, 1, 1, m0, o0, tid, Xh, Xl, Wh, Wl, Uh, Ul, BLh, BLl);

    for (int t = 0; t < NCHUNK; t++) {
        int stage = t & 1;
        cp_wait<1>();
        __syncthreads();

        const char* sx_h = smem + stage * STAGE_BYTES;
        const char* sx_l = sx_h + PLANE_BYTES;
        const char* sw_h = sx_h + 2 * PLANE_BYTES;
        const char* sw_l = sx_h + 3 * PLANE_BYTES;

        #pragma unroll
        for (int k16 = 0; k16 < 2; k16++) {
            int cbyte = (k16 * 16 + tq * 2) * 2;
            uint32_t bh[4][2], bl[4][2];
            #pragma unroll
            for (int ni = 0; ni < 4; ni++) {
                int nrow = wn + ni * 8 + g;
                size_t off = (size_t)nrow * ROWB + cbyte;
                bh[ni][0] = *(const uint32_t*)(sw_h + off);
                bh[ni][1] = *(const uint32_t*)(sw_h + off + 16);
                bl[ni][0] = *(const uint32_t*)(sw_l + off);
                bl[ni][1] = *(const uint32_t*)(sw_l + off + 16);
            }
            #pragma unroll
            for (int mi = 0; mi < 4; mi++) {
                int mrow = wm + mi * 16 + g;
                size_t a0 = (size_t)mrow * ROWB + cbyte;
                uint32_t ah[4], al[4];
                ah[0] = *(const uint32_t*)(sx_h + a0);
                ah[1] = *(const uint32_t*)(sx_h + a0 + 8 * ROWB);
                ah[2] = *(const uint32_t*)(sx_h + a0 + 16);
                ah[3] = *(const uint32_t*)(sx_h + a0 + 8 * ROWB + 16);
                al[0] = *(const uint32_t*)(sx_l + a0);
                al[1] = *(const uint32_t*)(sx_l + a0 + 8 * ROWB);
                al[2] = *(const uint32_t*)(sx_l + a0 + 16);
                al[3] = *(const uint32_t*)(sx_l + a0 + 8 * ROWB + 16);
                #pragma unroll
                for (int ni = 0; ni < 4; ni++) {
                    mma16816(acc[mi][ni], ah, bh[ni]);
                    mma16816(acc[mi][ni], ah, bl[ni]);
                    mma16816(acc[mi][ni], al, bh[ni]);
                }
            }
        }
        __syncthreads();
        if (t + 2 < NCHUNK)
            load_chunk(sb, stage, t + 2, m0, o0, tid,
                       Xh, Xl, Wh, Wl, Uh, Ul, BLh, BLl);
        else
            cp_commit();   // keep group accounting moving
    }

    // ---- epilogue ----
    #pragma unroll
    for (int mi = 0; mi < 4; mi++) {
        int r0 = m0 + wm + mi * 16 + g;
        #pragma unroll
        for (int ni = 0; ni < 4; ni++) {
            int c = o0 + wn + ni * 8 + tq * 2;
            float2 b2 = *(const float2*)(bias + c);
            float v0 = acc[mi][ni][0] + b2.x;
            float v1 = acc[mi][ni][1] + b2.y;
            float v2 = acc[mi][ni][2] + b2.x;
            float v3 = acc[mi][ni][3] + b2.y;
            if (Res) {
                float2 ra = *(const float2*)(Res + (size_t)r0 * CDIM + c);
                float2 rb = *(const float2*)(Res + (size_t)(r0 + 8) * CDIM + c);
                v0 += ra.x; v1 += ra.y; v2 += rb.x; v3 += rb.y;
            }
            if (do_relu) {
                v0 = fmaxf(v0, 0.f); v1 = fmaxf(v1, 0.f);
                v2 = fmaxf(v2, 0.f); v3 = fmaxf(v3, 0.f);
            }
            *(float2*)(OutF + (size_t)r0 * CDIM + c) = make_float2(v0, v1);
            *(float2*)(OutF + (size_t)(r0 + 8) * CDIM + c) = make_float2(v2, v3);
            if (OutH) {
                *(uint32_t*)(OutH + (size_t)r0 * CDIM + c) = pack_hi2(v0, v1);
                *(uint32_t*)(OutL + (size_t)r0 * CDIM + c) = pack_lo2(v0, v1);
                *(uint32_t*)(OutH + (size_t)(r0 + 8) * CDIM + c) = pack_hi2(v2, v3);
                *(uint32_t*)(OutL + (size_t)(r0 + 8) * CDIM + c) = pack_lo2(v2, v3);
            }
        }
    }
}

// ---------------- LayerNorm (+ bf16 plane output) ----------------
__global__ void layernorm_k(float* __restrict__ H,
                            const float* __restrict__ g,
                            const float* __restrict__ b,
                            bf16* __restrict__ OutH, bf16* __restrict__ OutL)
{
    __shared__ float red[16];
    int row = blockIdx.x;
    float4* hp = (float4*)(H + (size_t)row * CDIM);
    int tid = threadIdx.x;
    float4 x = hp[tid];

    float s = x.x + x.y + x.z + x.w;
    #pragma unroll
    for (int o = 16; o > 0; o >>= 1) s += __shfl_xor_sync(0xffffffffu, s, o);
    if ((tid & 31) == 0) red[tid >> 5] = s;
    __syncthreads();
    float tot = 0.f;
    #pragma unroll
    for (int w = 0; w < 8; w++) tot += red[w];
    float mean = tot * (1.f / 1024.f);

    float d0 = x.x - mean, d1 = x.y - mean, d2 = x.z - mean, d3 = x.w - mean;
    float sq = d0 * d0 + d1 * d1 + d2 * d2 + d3 * d3;
    #pragma unroll
    for (int o = 16; o > 0; o >>= 1) sq += __shfl_xor_sync(0xffffffffu, sq, o);
    if ((tid & 31) == 0) red[8 + (tid >> 5)] = sq;
    __syncthreads();
    float tot2 = 0.f;
    #pragma unroll
    for (int w = 0; w < 8; w++) tot2 += red[8 + w];
    float inv = rsqrtf(tot2 * (1.f / 1024.f) + 1e-5f);

    float4 gg = ((const float4*)g)[tid];
    float4 bb = ((const float4*)b)[tid];
    float4 y;
    y.x = d0 * inv * gg.x + bb.x;
    y.y = d1 * inv * gg.y + bb.y;
    y.z = d2 * inv * gg.z + bb.z;
    y.w = d3 * inv * gg.w + bb.w;
    hp[tid] = y;
    uint2 h; h.x = pack_hi2(y.x, y.y); h.y = pack_hi2(y.z, y.w);
    uint2 l; l.x = pack_lo2(y.x, y.y); l.y = pack_lo2(y.z, y.w);
    ((uint2*)(OutH + (size_t)row * CDIM))[tid] = h;
    ((uint2*)(OutL + (size_t)row * CDIM))[tid] = l;
}

// ---------------------------------------------------------------------------
extern "C" void kernel_launch(void* const* d_in, const int* in_sizes, int n_in,
                              void* d_out, int out_size)
{
    const float* x      = (const float*)d_in[0];
    const int*   qw     = (const int*)  d_in[1];
    const float* scales = (const float*)d_in[2];
    const float* bias   = (const float*)d_in[3];
    const float* la     = (const float*)d_in[4];
    const float* lb     = (const float*)d_in[5];
    const float* ln_g   = (const float*)d_in[6];
    const float* ln_b   = (const float*)d_in[7];
    float* out = (float*)d_out;

    bf16 *Whi, *Wlo, *Ah0, *Al0, *Ah1, *Al1, *Uh, *Ul, *BLh, *BLl;
    float *h, *t1, *t2, *up;
    cudaGetSymbolAddress((void**)&Whi, g_Whi);
    cudaGetSymbolAddress((void**)&Wlo, g_Wlo);
    cudaGetSymbolAddress((void**)&Ah0, g_Ah0);
    cudaGetSymbolAddress((void**)&Al0, g_Al0);
    cudaGetSymbolAddress((void**)&Ah1, g_Ah1);
    cudaGetSymbolAddress((void**)&Al1, g_Al1);
    cudaGetSymbolAddress((void**)&Uh,  g_Uh);
    cudaGetSymbolAddress((void**)&Ul,  g_Ul);
    cudaGetSymbolAddress((void**)&BLh, g_BLh);
    cudaGetSymbolAddress((void**)&BLl, g_BLl);
    cudaGetSymbolAddress((void**)&h,  g_h);
    cudaGetSymbolAddress((void**)&t1, g_t1);
    cudaGetSymbolAddress((void**)&t2, g_t2);
    cudaGetSymbolAddress((void**)&up, g_upart);

    cudaFuncSetAttribute(gemm_mma, cudaFuncAttributeMaxDynamicSharedMemorySize,
                         SMEM_TOTAL);

    dequant_whl<<<18432, 256>>>(qw, scales, Whi, Wlo, 4718592);
    prep_lb<<<4608, 256>>>(lb, BLh, BLl);
    prep_x<<<8192, 256>>>(x, Ah0, Al0);

    for (int blk = 0; blk < 6; ++blk) {
        const float* hin = blk ? h : x;
        for (int j = 0; j < 3; ++j) {
            int l = 3 * blk + j;
            const float* act = (j == 0) ? hin : ((j == 1) ? t1 : t2);
            lora_u_partial<<<dim3(64, 8), 256>>>(act, la + (size_t)l * RDIM * CDIM, up);
            lora_u_reduce<<<1024, 256>>>(up, Uh, Ul);

            const bf16* pXh = (l & 1) ? Ah1 : Ah0;
            const bf16* pXl = (l & 1) ? Al1 : Al0;
            bf16* oh = nullptr; bf16* ol = nullptr;
            float* of; const float* res = nullptr; int relu = (j < 2);
            if (j < 2) {
                of = (j == 0) ? t1 : t2;
                oh = (l & 1) ? Ah0 : Ah1;
                ol = (l & 1) ? Al0 : Al1;
            } else {
                of = (blk == 5) ? out : h;
                res = hin;
            }
            gemm_mma<<<dim3(8, 64), 256, SMEM_TOTAL>>>(
                pXh, pXl,
                Whi + ((size_t)l << 20), Wlo + ((size_t)l << 20),
                bias + (size_t)l * CDIM,
                Uh, Ul,
                BLh + (size_t)l * CDIM * 64, BLl + (size_t)l * CDIM * 64,
                res, of, oh, ol, relu);
        }
        if (blk < 5) {
            int ln = 3 * blk + 3;
            layernorm_k<<<NROWS, 256>>>(h, ln_g + (size_t)blk * CDIM,
                                        ln_b + (size_t)blk * CDIM,
                                        (ln & 1) ? Ah1 : Ah0,
                                        (ln & 1) ? Al1 : Al0);
        }
    }
}